// round 14
// baseline (speedup 1.0000x reference)
#include <cuda_runtime.h>
#include <math_constants.h>

#define HDIM   1536
#define NHEADS 12
#define NKV    2
#define DHEAD  128
#define GQA    6
#define MAXC   131072
#define QK_SCALE 0.08838834764831845f   // 128^-0.5

#define CS     256
#define NCHUNK (MAXC / CS)              // 512
#define NSPLIT 16

// ---- scratch (no allocs allowed) ----
__device__ float g_q   [NHEADS * DHEAD];
__device__ float g_kv  [2 * NKV * DHEAD];
__device__ float g_pm  [NHEADS * NCHUNK];            // [head][chunk]
__device__ float g_pz  [NHEADS * NCHUNK];
__device__ float g_w   [NHEADS * MAXC];              // exp-weights [head][pos]
__device__ float g_M   [NHEADS];
__device__ float g_Z   [NHEADS];
__device__ float g_out2[NSPLIT][NHEADS * DHEAD];     // atomic partials
__device__ float g_att [NHEADS * DHEAD];             // collapsed attention out

// =====================================================================
// K1: q/k/v projections (+ zero the atomic partials).
// 2048 rows; each row split across 2 warps, 4 rows/block, grid 512.
// =====================================================================
__global__ __launch_bounds__(256) void qkv_kernel(
    const float* __restrict__ x,
    const float* __restrict__ Wq,
    const float* __restrict__ Wk,
    const float* __restrict__ Wv)
{
    // zero partial buffers (grid-wide, independent of the GEMV work)
    {
        int i = blockIdx.x * 256 + threadIdx.x;
        if (i < NSPLIT * NHEADS * DHEAD / 4)
            ((float4*)g_out2)[i] = make_float4(0.f, 0.f, 0.f, 0.f);
    }

    __shared__ __align__(16) float xs[HDIM];
    __shared__ float rs[8];
    const int tid = threadIdx.x;
    for (int i = tid; i < HDIM / 4; i += 256)
        ((float4*)xs)[i] = ((const float4*)x)[i];
    __syncthreads();

    const int warp = tid >> 5, lane = tid & 31;
    const int rowInBlk = warp >> 1;            // 0..3
    const int half = warp & 1;                 // which 768-col half
    const int R = blockIdx.x * 4 + rowInBlk;   // 0..2047

    const float* Wrow;
    if (R < 1536)      Wrow = Wq + (long)R * HDIM;
    else if (R < 1792) Wrow = Wk + (long)(R - 1536) * HDIM;
    else               Wrow = Wv + (long)(R - 1792) * HDIM;

    const float4* W4 = (const float4*)Wrow + half * 192;   // 768 cols = 192 f4
    const float4* x4 = (const float4*)xs + half * 192;
    float s = 0.0f;
#pragma unroll
    for (int i = 0; i < 6; i++) {
        float4 a = W4[i * 32 + lane];
        float4 v = x4[i * 32 + lane];
        s += a.x * v.x + a.y * v.y + a.z * v.z + a.w * v.w;
    }
#pragma unroll
    for (int o = 16; o; o >>= 1) s += __shfl_xor_sync(0xffffffffu, s, o);
    if (lane == 0) rs[warp] = s;
    __syncthreads();

    if (tid < 4) {
        const int Rr = blockIdx.x * 4 + tid;
        float sum = rs[2 * tid] + rs[2 * tid + 1];
        if (Rr < 1536)      g_q[Rr] = sum * QK_SCALE;
        else if (Rr < 1792) g_kv[Rr - 1536] = sum;
        else                g_kv[NKV * DHEAD + (Rr - 1792)] = sum;
    }
}

// =====================================================================
// K2: scores + chunk softmax stats. Pure K stream.
// Half-warp head split. grid (NCHUNK, NKV), 256 threads, 3 blocks/SM.
// [R11 champion version, unchanged]
// =====================================================================
__global__ __launch_bounds__(256, 3) void score_kernel(
    const float* __restrict__ Kc,
    const int*   __restrict__ pos_p)
{
    __shared__ __align__(16) float qs[GQA * DHEAD];   // 3 KB
    __shared__ __align__(16) float ss[GQA][CS];       // 6 KB

    const int tid = threadIdx.x;
    const int c = blockIdx.x, g = blockIdx.y;
    const int pos = *pos_p;
    const int cb = c * CS;
    const int lane = tid & 31, warp = tid >> 5;

    for (int i = tid; i < GQA * DHEAD / 4; i += 256)
        ((float4*)qs)[i] = ((const float4*)(g_q + g * GQA * DHEAD))[i];
    __syncthreads();

    const int half = lane >> 4;            // head group: 0 -> h0..2, 1 -> h3..5
    const int sg   = (lane >> 3) & 1;      // position subgroup within half
    const int ll   = lane & 7;             // dim lanelet
    const int hb   = half * 3;

    // q registers: 3 heads x 4 float4 = 48 regs
    float4 qr[3][4];
    {
        const float4* q4 = (const float4*)qs;
#pragma unroll
        for (int hi = 0; hi < 3; hi++)
#pragma unroll
            for (int j = 0; j < 4; j++)
                qr[hi][j] = q4[(hb + hi) * 32 + j * 8 + ll];
    }

    const float* Kbase = Kc + (long)g * MAXC * DHEAD;

#pragma unroll 1
    for (int it = 0; it < CS / 16; ++it) {
        int li = it * 16 + warp * 2 + sg;
        int gl = cb + li;
        const float4* krow = (gl == pos)
            ? (const float4*)(g_kv + g * DHEAD)
            : (const float4*)(Kbase + (long)gl * DHEAD);
        float p0 = 0.f, p1 = 0.f, p2 = 0.f;
#pragma unroll
        for (int j = 0; j < 4; j++) {
            float4 k = krow[j * 8 + ll];
            p0 += qr[0][j].x * k.x + qr[0][j].y * k.y + qr[0][j].z * k.z + qr[0][j].w * k.w;
            p1 += qr[1][j].x * k.x + qr[1][j].y * k.y + qr[1][j].z * k.z + qr[1][j].w * k.w;
            p2 += qr[2][j].x * k.x + qr[2][j].y * k.y + qr[2][j].z * k.z + qr[2][j].w * k.w;
        }
#pragma unroll
        for (int o = 1; o < 8; o <<= 1) {
            p0 += __shfl_xor_sync(0xffffffffu, p0, o);
            p1 += __shfl_xor_sync(0xffffffffu, p1, o);
            p2 += __shfl_xor_sync(0xffffffffu, p2, o);
        }
        if (ll == 0) {
            bool valid = (gl <= pos);
            ss[hb + 0][li] = valid ? p0 : -CUDART_INF_F;
            ss[hb + 1][li] = valid ? p1 : -CUDART_INF_F;
            ss[hb + 2][li] = valid ? p2 : -CUDART_INF_F;
        }
    }
    __syncthreads();

    // per-head chunk max, exp, partial Z
    if (warp < GQA) {
        const int h = warp;
        float m = -CUDART_INF_F;
#pragma unroll
        for (int i = 0; i < CS / 32; i++) m = fmaxf(m, ss[h][lane + i * 32]);
#pragma unroll
        for (int o = 16; o; o >>= 1) m = fmaxf(m, __shfl_xor_sync(0xffffffffu, m, o));
        float mc = (m < -3e38f) ? 0.0f : m;
        float z = 0.0f;
#pragma unroll
        for (int i = 0; i < CS / 32; i++) {
            float e = __expf(ss[h][lane + i * 32] - mc);
            ss[h][lane + i * 32] = e;
            z += e;
        }
#pragma unroll
        for (int o = 16; o; o >>= 1) z += __shfl_xor_sync(0xffffffffu, z, o);
        if (lane == 0) {
            g_pm[(g * GQA + h) * NCHUNK + c] = m;
            g_pz[(g * GQA + h) * NCHUNK + c] = z;
        }
    }
    __syncthreads();

    // weight writeback (coalesced float4 per head row)
    for (int i = tid; i < GQA * CS / 4; i += 256) {
        int h  = i / (CS / 4);
        int d4 = i % (CS / 4);
        ((float4*)(g_w + (long)(g * GQA + h) * MAXC + cb))[d4] = ((float4*)ss[h])[d4];
    }
}

// =====================================================================
// K3: global M/Z per head. 1 block, 12 warps, contiguous float4.
// =====================================================================
__global__ __launch_bounds__(384) void mz_kernel()
{
    const int warp = threadIdx.x >> 5, lane = threadIdx.x & 31;
    const int hh = warp;

    const float4* pm4 = (const float4*)(g_pm + hh * NCHUNK);
    const float4* pz4 = (const float4*)(g_pz + hh * NCHUNK);

    float m = -CUDART_INF_F;
    float4 mv[NCHUNK / 128];
#pragma unroll
    for (int i = 0; i < NCHUNK / 128; i++) {
        mv[i] = pm4[i * 32 + lane];
        m = fmaxf(m, fmaxf(fmaxf(mv[i].x, mv[i].y), fmaxf(mv[i].z, mv[i].w)));
    }
#pragma unroll
    for (int o = 16; o; o >>= 1) m = fmaxf(m, __shfl_xor_sync(0xffffffffu, m, o));

    float z = 0.0f;
#pragma unroll
    for (int i = 0; i < NCHUNK / 128; i++) {
        float4 zv = pz4[i * 32 + lane];
        z += __expf(mv[i].x - m) * zv.x + __expf(mv[i].y - m) * zv.y
           + __expf(mv[i].z - m) * zv.z + __expf(mv[i].w - m) * zv.w;
    }
#pragma unroll
    for (int o = 16; o; o >>= 1) z += __shfl_xor_sync(0xffffffffu, z, o);
    if (lane == 0) { g_M[hh] = m; g_Z[hh] = z; }
}

// =====================================================================
// K4: weighted V accumulation. Pure V stream, smem cross-warp reduce,
// block-cooperative atomics. grid (NCHUNK, NKV), 256 threads.
// [R11 champion version, unchanged]
// =====================================================================
__global__ __launch_bounds__(256) void vacc_kernel(
    const float* __restrict__ Vc,
    const int*   __restrict__ pos_p)
{
    __shared__ __align__(16) float ss[GQA][CS];         // 6 KB
    __shared__ __align__(16) float buf[8][GQA * DHEAD]; // 24 KB

    const int tid = threadIdx.x;
    const int c = blockIdx.x, g = blockIdx.y;
    const int pos = *pos_p;
    const int cb = c * CS;
    const int lane = tid & 31, warp = tid >> 5;

    // load weights for this chunk
    for (int i = tid; i < GQA * CS / 4; i += 256) {
        int h  = i / (CS / 4);
        int d4 = i % (CS / 4);
        ((float4*)ss[h])[d4] = ((const float4*)(g_w + (long)(g * GQA + h) * MAXC + cb))[d4];
    }
    __syncthreads();

    // warp-per-position float4 V accumulate
    const float* Vbase = Vc + (long)g * MAXC * DHEAD;
    const float4* vnew4 = (const float4*)(g_kv + NKV * DHEAD + g * DHEAD);
    float4 acc[GQA];
#pragma unroll
    for (int h = 0; h < GQA; h++) acc[h] = make_float4(0.f, 0.f, 0.f, 0.f);

#pragma unroll 4
    for (int l = warp; l < CS; l += 8) {
        int gl = cb + l;
        float4 v = (gl == pos) ? vnew4[lane]
                               : ((const float4*)(Vbase + (long)gl * DHEAD))[lane];
        float e[GQA];
#pragma unroll
        for (int h = 0; h < GQA; h++) e[h] = ss[h][l];
#pragma unroll
        for (int h = 0; h < GQA; h++) {
            acc[h].x += e[h] * v.x;
            acc[h].y += e[h] * v.y;
            acc[h].z += e[h] * v.z;
            acc[h].w += e[h] * v.w;
        }
    }
    float4* b4 = (float4*)buf[warp];
#pragma unroll
    for (int h = 0; h < GQA; h++) b4[h * 32 + lane] = acc[h];
    __syncthreads();

    // cross-warp reduce, rescale by exp(pm-M)/Z, atomic-add into partials
    const int s = c & (NSPLIT - 1);
    for (int i = tid; i < GQA * DHEAD / 4; i += 256) {
        float4 sum = ((float4*)buf[0])[i];
#pragma unroll
        for (int w = 1; w < 8; w++) {
            float4 t = ((float4*)buf[w])[i];
            sum.x += t.x; sum.y += t.y; sum.z += t.z; sum.w += t.w;
        }
        int h  = i >> 5;
        int d4 = i & 31;
        int hh = g * GQA + h;
        float f = __expf(g_pm[hh * NCHUNK + c] - g_M[hh]) * (1.0f / g_Z[hh]);
        float* dst = g_out2[s] + hh * DHEAD + d4 * 4;
        atomicAdd(dst + 0, sum.x * f);
        atomicAdd(dst + 1, sum.y * f);
        atomicAdd(dst + 2, sum.z * f);
        atomicAdd(dst + 3, sum.w * f);
    }
}

// =====================================================================
// K5: collapse the 16 partial buffers into g_att (once, chip-wide).
// grid 3 x 128; each thread owns one float4 of the 384.
// =====================================================================
__global__ __launch_bounds__(128) void prenorm_kernel()
{
    const int i4 = blockIdx.x * 128 + threadIdx.x;   // 0..383
    float4 s = make_float4(0.f, 0.f, 0.f, 0.f);
#pragma unroll
    for (int p = 0; p < NSPLIT; p++) {
        float4 t = ((const float4*)g_out2[p])[i4];
        s.x += t.x; s.y += t.y; s.z += t.z; s.w += t.w;
    }
    ((float4*)g_att)[i4] = s;
}

// =====================================================================
// K6: y = Wo @ g_att. 384 blocks x 4 rows; row = 2 warps (half-row
// dots), smem combine, no atomics. Prologue is now a 6 KB L2-hot read.
// =====================================================================
__global__ __launch_bounds__(256) void oproj_kernel(
    const float* __restrict__ Wo, float* __restrict__ y)
{
    __shared__ __align__(16) float os[HDIM];
    __shared__ float rsum[8];
    const int tid = threadIdx.x;

    for (int i4 = tid; i4 < HDIM / 4; i4 += 256)
        ((float4*)os)[i4] = ((const float4*)g_att)[i4];
    __syncthreads();

    const int warp = tid >> 5, lane = tid & 31;
    const int row  = blockIdx.x * 4 + (warp >> 1);
    const int halfsel = warp & 1;

    const float4* W4 = (const float4*)(Wo + (long)row * HDIM + halfsel * (HDIM / 2));
    const float4* o4 = (const float4*)(os + halfsel * (HDIM / 2));
    float s = 0.0f;
#pragma unroll
    for (int i = 0; i < 6; i++) {
        float4 a = W4[i * 32 + lane];
        float4 v = o4[i * 32 + lane];
        s += a.x * v.x + a.y * v.y + a.z * v.z + a.w * v.w;
    }
#pragma unroll
    for (int o = 16; o; o >>= 1) s += __shfl_xor_sync(0xffffffffu, s, o);
    if (lane == 0) rsum[warp] = s;
    __syncthreads();

    if (tid < 4)
        y[blockIdx.x * 4 + tid] = rsum[2 * tid] + rsum[2 * tid + 1];
}

// =====================================================================
// launch
// =====================================================================
extern "C" void kernel_launch(void* const* d_in, const int* in_sizes, int n_in,
                              void* d_out, int out_size)
{
    const float* x   = (const float*)d_in[0];
    const float* Wq  = (const float*)d_in[1];
    const float* Wk  = (const float*)d_in[2];
    const float* Wv  = (const float*)d_in[3];
    const float* Wo  = (const float*)d_in[4];
    const float* Kc  = (const float*)d_in[5];
    const float* Vc  = (const float*)d_in[6];
    const int*   pos = (const int*)d_in[7];

    qkv_kernel<<<512, 256>>>(x, Wq, Wk, Wv);
    score_kernel<<<dim3(NCHUNK, NKV), 256>>>(Kc, pos);
    mz_kernel<<<1, 384>>>();
    vacc_kernel<<<dim3(NCHUNK, NKV), 256>>>(Vc, pos);
    prenorm_kernel<<<3, 128>>>();
    oproj_kernel<<<HDIM / 4, 256>>>(Wo, (float*)d_out);
}

// round 15
// speedup vs baseline: 1.3271x; 1.3271x over previous
#include <cuda_runtime.h>
#include <math_constants.h>

#define HDIM   1536
#define NHEADS 12
#define NKV    2
#define DHEAD  128
#define GQA    6
#define MAXC   131072
#define QK_SCALE 0.08838834764831845f   // 128^-0.5

#define CS     256
#define NCHUNK (MAXC / CS)              // 512
#define NSPLIT 16

// ---- scratch (no allocs allowed) ----
__device__ float g_q   [NHEADS * DHEAD];
__device__ float g_kv  [2 * NKV * DHEAD];
__device__ float g_pm  [NHEADS * NCHUNK];            // [head][chunk]
__device__ float g_pz  [NHEADS * NCHUNK];
__device__ float g_w   [NHEADS * MAXC];              // exp-weights [head][pos]
__device__ float g_M   [NHEADS];
__device__ float g_Z   [NHEADS];
__device__ float g_out2[NSPLIT][NHEADS * DHEAD];     // atomic partials
__device__ float g_att [NHEADS * DHEAD];             // collapsed attention out

// =====================================================================
// K1: q/k/v projections (+ zero the atomic partials).
// 2048 rows; each row split across 2 warps, 4 rows/block, grid 512.
// =====================================================================
__global__ __launch_bounds__(256) void qkv_kernel(
    const float* __restrict__ x,
    const float* __restrict__ Wq,
    const float* __restrict__ Wk,
    const float* __restrict__ Wv)
{
    // zero partial buffers (grid-wide, independent of the GEMV work)
    {
        int i = blockIdx.x * 256 + threadIdx.x;
        if (i < NSPLIT * NHEADS * DHEAD / 4)
            ((float4*)g_out2)[i] = make_float4(0.f, 0.f, 0.f, 0.f);
    }

    __shared__ __align__(16) float xs[HDIM];
    __shared__ float rs[8];
    const int tid = threadIdx.x;
    for (int i = tid; i < HDIM / 4; i += 256)
        ((float4*)xs)[i] = ((const float4*)x)[i];
    __syncthreads();

    const int warp = tid >> 5, lane = tid & 31;
    const int rowInBlk = warp >> 1;            // 0..3
    const int half = warp & 1;                 // which 768-col half
    const int R = blockIdx.x * 4 + rowInBlk;   // 0..2047

    const float* Wrow;
    if (R < 1536)      Wrow = Wq + (long)R * HDIM;
    else if (R < 1792) Wrow = Wk + (long)(R - 1536) * HDIM;
    else               Wrow = Wv + (long)(R - 1792) * HDIM;

    const float4* W4 = (const float4*)Wrow + half * 192;   // 768 cols = 192 f4
    const float4* x4 = (const float4*)xs + half * 192;
    float s = 0.0f;
#pragma unroll
    for (int i = 0; i < 6; i++) {
        float4 a = W4[i * 32 + lane];
        float4 v = x4[i * 32 + lane];
        s += a.x * v.x + a.y * v.y + a.z * v.z + a.w * v.w;
    }
#pragma unroll
    for (int o = 16; o; o >>= 1) s += __shfl_xor_sync(0xffffffffu, s, o);
    if (lane == 0) rs[warp] = s;
    __syncthreads();

    if (tid < 4) {
        const int Rr = blockIdx.x * 4 + tid;
        float sum = rs[2 * tid] + rs[2 * tid + 1];
        if (Rr < 1536)      g_q[Rr] = sum * QK_SCALE;
        else if (Rr < 1792) g_kv[Rr - 1536] = sum;
        else                g_kv[NKV * DHEAD + (Rr - 1792)] = sum;
    }
}

// =====================================================================
// K2: scores + chunk softmax stats. Pure K stream.
// Half-warp head split (champion hot loop). Phase 2 writes exp-weights
// STRAIGHT to g_w from registers (coalesced) — no smem re-store, no
// third sweep, one fewer barrier.
// grid (NCHUNK, NKV), 256 threads, 3 blocks/SM.
// =====================================================================
__global__ __launch_bounds__(256, 3) void score_kernel(
    const float* __restrict__ Kc,
    const int*   __restrict__ pos_p)
{
    __shared__ __align__(16) float qs[GQA * DHEAD];   // 3 KB
    __shared__ __align__(16) float ss[GQA][CS];       // 6 KB

    const int tid = threadIdx.x;
    const int c = blockIdx.x, g = blockIdx.y;
    const int pos = *pos_p;
    const int cb = c * CS;
    const int lane = tid & 31, warp = tid >> 5;

    for (int i = tid; i < GQA * DHEAD / 4; i += 256)
        ((float4*)qs)[i] = ((const float4*)(g_q + g * GQA * DHEAD))[i];
    __syncthreads();

    const int half = lane >> 4;            // head group: 0 -> h0..2, 1 -> h3..5
    const int sg   = (lane >> 3) & 1;      // position subgroup within half
    const int ll   = lane & 7;             // dim lanelet
    const int hb   = half * 3;

    // q registers: 3 heads x 4 float4 = 48 regs
    float4 qr[3][4];
    {
        const float4* q4 = (const float4*)qs;
#pragma unroll
        for (int hi = 0; hi < 3; hi++)
#pragma unroll
            for (int j = 0; j < 4; j++)
                qr[hi][j] = q4[(hb + hi) * 32 + j * 8 + ll];
    }

    const float* Kbase = Kc + (long)g * MAXC * DHEAD;

#pragma unroll 1
    for (int it = 0; it < CS / 16; ++it) {
        int li = it * 16 + warp * 2 + sg;
        int gl = cb + li;
        const float4* krow = (gl == pos)
            ? (const float4*)(g_kv + g * DHEAD)
            : (const float4*)(Kbase + (long)gl * DHEAD);
        float p0 = 0.f, p1 = 0.f, p2 = 0.f;
#pragma unroll
        for (int j = 0; j < 4; j++) {
            float4 k = krow[j * 8 + ll];
            p0 += qr[0][j].x * k.x + qr[0][j].y * k.y + qr[0][j].z * k.z + qr[0][j].w * k.w;
            p1 += qr[1][j].x * k.x + qr[1][j].y * k.y + qr[1][j].z * k.z + qr[1][j].w * k.w;
            p2 += qr[2][j].x * k.x + qr[2][j].y * k.y + qr[2][j].z * k.z + qr[2][j].w * k.w;
        }
#pragma unroll
        for (int o = 1; o < 8; o <<= 1) {
            p0 += __shfl_xor_sync(0xffffffffu, p0, o);
            p1 += __shfl_xor_sync(0xffffffffu, p1, o);
            p2 += __shfl_xor_sync(0xffffffffu, p2, o);
        }
        if (ll == 0) {
            bool valid = (gl <= pos);
            ss[hb + 0][li] = valid ? p0 : -CUDART_INF_F;
            ss[hb + 1][li] = valid ? p1 : -CUDART_INF_F;
            ss[hb + 2][li] = valid ? p2 : -CUDART_INF_F;
        }
    }
    __syncthreads();

    // per-head chunk max, exp (written straight to g_w), partial Z
    if (warp < GQA) {
        const int h = warp;
        float m = -CUDART_INF_F;
#pragma unroll
        for (int i = 0; i < CS / 32; i++) m = fmaxf(m, ss[h][lane + i * 32]);
#pragma unroll
        for (int o = 16; o; o >>= 1) m = fmaxf(m, __shfl_xor_sync(0xffffffffu, m, o));
        float mc = (m < -3e38f) ? 0.0f : m;
        float z = 0.0f;
        float* wrow = g_w + (long)(g * GQA + h) * MAXC + cb;
#pragma unroll
        for (int i = 0; i < CS / 32; i++) {
            float e = __expf(ss[h][lane + i * 32] - mc);
            wrow[lane + i * 32] = e;          // coalesced 128B per warp-iter
            z += e;
        }
#pragma unroll
        for (int o = 16; o; o >>= 1) z += __shfl_xor_sync(0xffffffffu, z, o);
        if (lane == 0) {
            g_pm[(g * GQA + h) * NCHUNK + c] = m;
            g_pz[(g * GQA + h) * NCHUNK + c] = z;
        }
    }
}

// =====================================================================
// K3: global M/Z per head. 1 block, 12 warps, contiguous float4.
// =====================================================================
__global__ __launch_bounds__(384) void mz_kernel()
{
    const int warp = threadIdx.x >> 5, lane = threadIdx.x & 31;
    const int hh = warp;

    const float4* pm4 = (const float4*)(g_pm + hh * NCHUNK);
    const float4* pz4 = (const float4*)(g_pz + hh * NCHUNK);

    float m = -CUDART_INF_F;
    float4 mv[NCHUNK / 128];
#pragma unroll
    for (int i = 0; i < NCHUNK / 128; i++) {
        mv[i] = pm4[i * 32 + lane];
        m = fmaxf(m, fmaxf(fmaxf(mv[i].x, mv[i].y), fmaxf(mv[i].z, mv[i].w)));
    }
#pragma unroll
    for (int o = 16; o; o >>= 1) m = fmaxf(m, __shfl_xor_sync(0xffffffffu, m, o));

    float z = 0.0f;
#pragma unroll
    for (int i = 0; i < NCHUNK / 128; i++) {
        float4 zv = pz4[i * 32 + lane];
        z += __expf(mv[i].x - m) * zv.x + __expf(mv[i].y - m) * zv.y
           + __expf(mv[i].z - m) * zv.z + __expf(mv[i].w - m) * zv.w;
    }
#pragma unroll
    for (int o = 16; o; o >>= 1) z += __shfl_xor_sync(0xffffffffu, z, o);
    if (lane == 0) { g_M[hh] = m; g_Z[hh] = z; }
}

// =====================================================================
// K4: weighted V accumulation. Pure V stream, smem cross-warp reduce,
// block-cooperative atomics. grid (NCHUNK, NKV), 256 threads.
// [champion version, unchanged]
// =====================================================================
__global__ __launch_bounds__(256) void vacc_kernel(
    const float* __restrict__ Vc,
    const int*   __restrict__ pos_p)
{
    __shared__ __align__(16) float ss[GQA][CS];         // 6 KB
    __shared__ __align__(16) float buf[8][GQA * DHEAD]; // 24 KB

    const int tid = threadIdx.x;
    const int c = blockIdx.x, g = blockIdx.y;
    const int pos = *pos_p;
    const int cb = c * CS;
    const int lane = tid & 31, warp = tid >> 5;

    // load weights for this chunk
    for (int i = tid; i < GQA * CS / 4; i += 256) {
        int h  = i / (CS / 4);
        int d4 = i % (CS / 4);
        ((float4*)ss[h])[d4] = ((const float4*)(g_w + (long)(g * GQA + h) * MAXC + cb))[d4];
    }
    __syncthreads();

    // warp-per-position float4 V accumulate
    const float* Vbase = Vc + (long)g * MAXC * DHEAD;
    const float4* vnew4 = (const float4*)(g_kv + NKV * DHEAD + g * DHEAD);
    float4 acc[GQA];
#pragma unroll
    for (int h = 0; h < GQA; h++) acc[h] = make_float4(0.f, 0.f, 0.f, 0.f);

#pragma unroll 4
    for (int l = warp; l < CS; l += 8) {
        int gl = cb + l;
        float4 v = (gl == pos) ? vnew4[lane]
                               : ((const float4*)(Vbase + (long)gl * DHEAD))[lane];
        float e[GQA];
#pragma unroll
        for (int h = 0; h < GQA; h++) e[h] = ss[h][l];
#pragma unroll
        for (int h = 0; h < GQA; h++) {
            acc[h].x += e[h] * v.x;
            acc[h].y += e[h] * v.y;
            acc[h].z += e[h] * v.z;
            acc[h].w += e[h] * v.w;
        }
    }
    float4* b4 = (float4*)buf[warp];
#pragma unroll
    for (int h = 0; h < GQA; h++) b4[h * 32 + lane] = acc[h];
    __syncthreads();

    // cross-warp reduce, rescale by exp(pm-M)/Z, atomic-add into partials
    const int s = c & (NSPLIT - 1);
    for (int i = tid; i < GQA * DHEAD / 4; i += 256) {
        float4 sum = ((float4*)buf[0])[i];
#pragma unroll
        for (int w = 1; w < 8; w++) {
            float4 t = ((float4*)buf[w])[i];
            sum.x += t.x; sum.y += t.y; sum.z += t.z; sum.w += t.w;
        }
        int h  = i >> 5;
        int d4 = i & 31;
        int hh = g * GQA + h;
        float f = __expf(g_pm[hh * NCHUNK + c] - g_M[hh]) * (1.0f / g_Z[hh]);
        float* dst = g_out2[s] + hh * DHEAD + d4 * 4;
        atomicAdd(dst + 0, sum.x * f);
        atomicAdd(dst + 1, sum.y * f);
        atomicAdd(dst + 2, sum.z * f);
        atomicAdd(dst + 3, sum.w * f);
    }
}

// =====================================================================
// K5: collapse the 16 partial buffers into g_att (once, chip-wide).
// grid 3 x 128; each thread owns one float4 of the 384.
// =====================================================================
__global__ __launch_bounds__(128) void prenorm_kernel()
{
    const int i4 = blockIdx.x * 128 + threadIdx.x;   // 0..383
    float4 s = make_float4(0.f, 0.f, 0.f, 0.f);
#pragma unroll
    for (int p = 0; p < NSPLIT; p++) {
        float4 t = ((const float4*)g_out2[p])[i4];
        s.x += t.x; s.y += t.y; s.z += t.z; s.w += t.w;
    }
    ((float4*)g_att)[i4] = s;
}

// =====================================================================
// K6: y = Wo @ g_att. 384 blocks x 4 rows; row = 2 warps (half-row
// dots), smem combine, no atomics. Prologue is a 6 KB L2-hot read.
// =====================================================================
__global__ __launch_bounds__(256) void oproj_kernel(
    const float* __restrict__ Wo, float* __restrict__ y)
{
    __shared__ __align__(16) float os[HDIM];
    __shared__ float rsum[8];
    const int tid = threadIdx.x;

    for (int i4 = tid; i4 < HDIM / 4; i4 += 256)
        ((float4*)os)[i4] = ((const float4*)g_att)[i4];
    __syncthreads();

    const int warp = tid >> 5, lane = tid & 31;
    const int row  = blockIdx.x * 4 + (warp >> 1);
    const int halfsel = warp & 1;

    const float4* W4 = (const float4*)(Wo + (long)row * HDIM + halfsel * (HDIM / 2));
    const float4* o4 = (const float4*)(os + halfsel * (HDIM / 2));
    float s = 0.0f;
#pragma unroll
    for (int i = 0; i < 6; i++) {
        float4 a = W4[i * 32 + lane];
        float4 v = o4[i * 32 + lane];
        s += a.x * v.x + a.y * v.y + a.z * v.z + a.w * v.w;
    }
#pragma unroll
    for (int o = 16; o; o >>= 1) s += __shfl_xor_sync(0xffffffffu, s, o);
    if (lane == 0) rsum[warp] = s;
    __syncthreads();

    if (tid < 4)
        y[blockIdx.x * 4 + tid] = rsum[2 * tid] + rsum[2 * tid + 1];
}

// =====================================================================
// launch
// =====================================================================
extern "C" void kernel_launch(void* const* d_in, const int* in_sizes, int n_in,
                              void* d_out, int out_size)
{
    const float* x   = (const float*)d_in[0];
    const float* Wq  = (const float*)d_in[1];
    const float* Wk  = (const float*)d_in[2];
    const float* Wv  = (const float*)d_in[3];
    const float* Wo  = (const float*)d_in[4];
    const float* Kc  = (const float*)d_in[5];
    const float* Vc  = (const float*)d_in[6];
    const int*   pos = (const int*)d_in[7];

    qkv_kernel<<<512, 256>>>(x, Wq, Wk, Wv);
    score_kernel<<<dim3(NCHUNK, NKV), 256>>>(Kc, pos);
    mz_kernel<<<1, 384>>>();
    vacc_kernel<<<dim3(NCHUNK, NKV), 256>>>(Vc, pos);
    prenorm_kernel<<<3, 128>>>();
    oproj_kernel<<<HDIM / 4, 256>>>(Wo, (float*)d_out);
}